// round 1
// baseline (speedup 1.0000x reference)
#include <cuda_runtime.h>
#include <cuda_bf16.h>

#define BB   512
#define ENC  512
#define ATT  512
#define ND   1024

__device__ float g_att1[BB * ATT];
__device__ float g_att2[BB * ATT];
__device__ float g_att [BB * BB];
__device__ float g_iw  [BB * ENC];
__device__ float g_inp [BB * ND];
__device__ float g_zb  [ND];          // zero bias

#define BM 64
#define BN 64
#define BKT 16

// EPI 0: v = acc + bias
// EPI 1: v = (acc + bias) * extra[row,col]
// EPI 2: v = relu(acc + bias + extra[row,col])
template <int EPI>
__global__ void gemm64(const float* __restrict__ A, const float* __restrict__ B,
                       const float* __restrict__ bias, const float* __restrict__ extra,
                       float* __restrict__ C, int M, int N, int K) {
    __shared__ float As[BM][BKT];
    __shared__ float Bs[BKT][BN];
    const int tx = threadIdx.x, ty = threadIdx.y;
    const int tid = ty * 16 + tx;
    const int bm = blockIdx.y * BM, bn = blockIdx.x * BN;

    float acc[4][4] = {};

    for (int k0 = 0; k0 < K; k0 += BKT) {
        #pragma unroll
        for (int i = 0; i < 4; i++) {
            int idx = tid + i * 256;
            int r = idx >> 4, c = idx & 15;
            As[r][c] = A[(size_t)(bm + r) * K + k0 + c];
        }
        #pragma unroll
        for (int i = 0; i < 4; i++) {
            int idx = tid + i * 256;
            int r = idx >> 6, c = idx & 63;
            Bs[r][c] = B[(size_t)(k0 + r) * N + bn + c];
        }
        __syncthreads();
        #pragma unroll
        for (int kk = 0; kk < BKT; kk++) {
            float a0 = As[ty * 4 + 0][kk];
            float a1 = As[ty * 4 + 1][kk];
            float a2 = As[ty * 4 + 2][kk];
            float a3 = As[ty * 4 + 3][kk];
            float4 b = *(const float4*)&Bs[kk][tx * 4];
            acc[0][0] += a0 * b.x; acc[0][1] += a0 * b.y; acc[0][2] += a0 * b.z; acc[0][3] += a0 * b.w;
            acc[1][0] += a1 * b.x; acc[1][1] += a1 * b.y; acc[1][2] += a1 * b.z; acc[1][3] += a1 * b.w;
            acc[2][0] += a2 * b.x; acc[2][1] += a2 * b.y; acc[2][2] += a2 * b.z; acc[2][3] += a2 * b.w;
            acc[3][0] += a3 * b.x; acc[3][1] += a3 * b.y; acc[3][2] += a3 * b.z; acc[3][3] += a3 * b.w;
        }
        __syncthreads();
    }

    #pragma unroll
    for (int i = 0; i < 4; i++) {
        int row = bm + ty * 4 + i;
        #pragma unroll
        for (int j = 0; j < 4; j++) {
            int col = bn + tx * 4 + j;
            float v = acc[i][j] + bias[col];
            if (EPI == 1) v = v * extra[(size_t)row * N + col];
            if (EPI == 2) v = fmaxf(v + extra[(size_t)row * N + col], 0.0f);
            C[(size_t)row * N + col] = v;
        }
    }
}

// att[q,k] = sum_c relu(att1[k,c] + att2[q,c]) * Wf[c]   (bf dropped: softmax-invariant)
__global__ void attcore_kernel(const float* __restrict__ att1, const float* __restrict__ att2,
                               const float* __restrict__ Wf, float* __restrict__ att) {
    __shared__ float Aq[64][BKT];
    __shared__ float Akt[BKT][64 + 1];
    __shared__ float ws[BKT];
    const int tx = threadIdx.x, ty = threadIdx.y;
    const int tid = ty * 16 + tx;
    const int bq = blockIdx.y * 64, bk = blockIdx.x * 64;

    float acc[4][4] = {};

    for (int c0 = 0; c0 < ATT; c0 += BKT) {
        #pragma unroll
        for (int i = 0; i < 4; i++) {
            int idx = tid + i * 256;
            int r = idx >> 4, c = idx & 15;
            Aq[r][c] = att2[(size_t)(bq + r) * ATT + c0 + c];
            Akt[c][r] = att1[(size_t)(bk + r) * ATT + c0 + c];
        }
        if (tid < BKT) ws[tid] = Wf[c0 + tid];
        __syncthreads();
        #pragma unroll
        for (int cc = 0; cc < BKT; cc++) {
            float wv = ws[cc];
            float aq0 = Aq[ty * 4 + 0][cc];
            float aq1 = Aq[ty * 4 + 1][cc];
            float aq2 = Aq[ty * 4 + 2][cc];
            float aq3 = Aq[ty * 4 + 3][cc];
            float ak0 = Akt[cc][tx * 4 + 0];
            float ak1 = Akt[cc][tx * 4 + 1];
            float ak2 = Akt[cc][tx * 4 + 2];
            float ak3 = Akt[cc][tx * 4 + 3];
            acc[0][0] += fmaxf(aq0 + ak0, 0.f) * wv; acc[0][1] += fmaxf(aq0 + ak1, 0.f) * wv;
            acc[0][2] += fmaxf(aq0 + ak2, 0.f) * wv; acc[0][3] += fmaxf(aq0 + ak3, 0.f) * wv;
            acc[1][0] += fmaxf(aq1 + ak0, 0.f) * wv; acc[1][1] += fmaxf(aq1 + ak1, 0.f) * wv;
            acc[1][2] += fmaxf(aq1 + ak2, 0.f) * wv; acc[1][3] += fmaxf(aq1 + ak3, 0.f) * wv;
            acc[2][0] += fmaxf(aq2 + ak0, 0.f) * wv; acc[2][1] += fmaxf(aq2 + ak1, 0.f) * wv;
            acc[2][2] += fmaxf(aq2 + ak2, 0.f) * wv; acc[2][3] += fmaxf(aq2 + ak3, 0.f) * wv;
            acc[3][0] += fmaxf(aq3 + ak0, 0.f) * wv; acc[3][1] += fmaxf(aq3 + ak1, 0.f) * wv;
            acc[3][2] += fmaxf(aq3 + ak2, 0.f) * wv; acc[3][3] += fmaxf(aq3 + ak3, 0.f) * wv;
        }
        __syncthreads();
    }
    #pragma unroll
    for (int i = 0; i < 4; i++)
        #pragma unroll
        for (int j = 0; j < 4; j++)
            att[(size_t)(bq + ty * 4 + i) * BB + bk + tx * 4 + j] = acc[i][j];
}

__global__ void softmax_kernel(float* __restrict__ att) {
    const int row = blockIdx.x;
    const int t = threadIdx.x;   // 128 threads
    __shared__ float red[4];
    float v[4];
    float m = -1e30f;
    #pragma unroll
    for (int i = 0; i < 4; i++) {
        v[i] = att[(size_t)row * BB + t + i * 128];
        m = fmaxf(m, v[i]);
    }
    #pragma unroll
    for (int o = 16; o; o >>= 1) m = fmaxf(m, __shfl_xor_sync(~0u, m, o));
    if ((t & 31) == 0) red[t >> 5] = m;
    __syncthreads();
    m = fmaxf(fmaxf(red[0], red[1]), fmaxf(red[2], red[3]));
    float s = 0.f;
    #pragma unroll
    for (int i = 0; i < 4; i++) { v[i] = __expf(v[i] - m); s += v[i]; }
    #pragma unroll
    for (int o = 16; o; o >>= 1) s += __shfl_xor_sync(~0u, s, o);
    __syncthreads();
    if ((t & 31) == 0) red[t >> 5] = s;
    __syncthreads();
    s = red[0] + red[1] + red[2] + red[3];
    float inv = 1.0f / s;
    #pragma unroll
    for (int i = 0; i < 4; i++)
        att[(size_t)row * BB + t + i * 128] = v[i] * inv;
}

__global__ void zero_bias_kernel() {
    int i = blockIdx.x * blockDim.x + threadIdx.x;
    if (i < ND) g_zb[i] = 0.0f;
}

__global__ void out_kernel(const float* __restrict__ ns, const float* __restrict__ W3,
                           const float* __restrict__ b3, float* __restrict__ out) {
    int gtid = blockIdx.x * blockDim.x + threadIdx.x;
    int row = gtid >> 5;
    int lane = gtid & 31;
    if (row >= BB) return;
    float s0 = 0.f, s1 = 0.f;
    for (int k = lane; k < ND; k += 32) {
        float v = ns[(size_t)row * ND + k];
        s0 += v * W3[k * 2 + 0];
        s1 += v * W3[k * 2 + 1];
    }
    #pragma unroll
    for (int o = 16; o; o >>= 1) {
        s0 += __shfl_down_sync(~0u, s0, o);
        s1 += __shfl_down_sync(~0u, s1, o);
    }
    if (lane == 0) {
        out[row * 2 + 0] = s0 + b3[0];
        out[row * 2 + 1] = s1 + b3[1];
    }
}

extern "C" void kernel_launch(void* const* d_in, const int* in_sizes, int n_in,
                              void* d_out, int out_size) {
    const float* x     = (const float*)d_in[0];
    const float* state = (const float*)d_in[1];
    const float* We    = (const float*)d_in[2];
    const float* be    = (const float*)d_in[3];
    const float* Wd    = (const float*)d_in[4];
    const float* bd    = (const float*)d_in[5];
    const float* Wf    = (const float*)d_in[6];
    // d_in[7] = bf : constant shift of softmax logits, mathematically irrelevant
    const float* W1    = (const float*)d_in[8];
    const float* b1    = (const float*)d_in[9];
    const float* W2    = (const float*)d_in[10];
    const float* b2    = (const float*)d_in[11];
    const float* W3    = (const float*)d_in[12];
    const float* b3    = (const float*)d_in[13];

    float* out = (float*)d_out;              // [0,1024): output ; then new_state (512x1024)
    float* new_state = out + BB * 2;

    float *att1, *att2, *att, *iw, *inp, *zb;
    cudaGetSymbolAddress((void**)&att1, g_att1);
    cudaGetSymbolAddress((void**)&att2, g_att2);
    cudaGetSymbolAddress((void**)&att,  g_att);
    cudaGetSymbolAddress((void**)&iw,   g_iw);
    cudaGetSymbolAddress((void**)&inp,  g_inp);
    cudaGetSymbolAddress((void**)&zb,   g_zb);

    dim3 blk(16, 16);

    zero_bias_kernel<<<(ND + 255) / 256, 256>>>();
    gemm64<0><<<dim3(ATT / BN, BB / BM), blk>>>(x, We, be, nullptr, att1, BB, ATT, ENC);
    gemm64<0><<<dim3(ATT / BN, BB / BM), blk>>>(state, Wd, bd, nullptr, att2, BB, ATT, ND);
    attcore_kernel<<<dim3(BB / 64, BB / 64), blk>>>(att1, att2, Wf, att);
    softmax_kernel<<<BB, 128>>>(att);
    gemm64<1><<<dim3(ENC / BN, BB / BM), blk>>>(att, x, zb, x, iw, BB, ENC, BB);
    gemm64<0><<<dim3(ND / BN, BB / BM), blk>>>(iw, W1, b1, nullptr, inp, BB, ND, ENC);
    gemm64<2><<<dim3(ND / BN, BB / BM), blk>>>(state, W2, b2, inp, new_state, BB, ND, ND);
    out_kernel<<<(BB * 32 + 255) / 256, 256>>>(new_state, W3, b3, out);
}

// round 2
// speedup vs baseline: 2.1809x; 2.1809x over previous
#include <cuda_runtime.h>
#include <cuda_bf16.h>

#define BB   512
#define ENC  512
#define ATT  512
#define ND   1024

typedef unsigned long long ull;

// ---------------- scratch ----------------
__device__ float g_att1p[2 * BB * ATT];   // x@We partials (K split 2)
__device__ float g_att2p[4 * BB * ATT];   // state@Wd partials (K split 4)
__device__ float g_stp  [4 * BB * ND];    // state@W2 partials (K split 4)
__device__ float g_att1 [BB * ATT];
__device__ float g_att2 [BB * ATT];
__device__ float g_attp [4 * BB * BB];    // logits partials (channel split 4)
__device__ float g_att  [BB * BB];        // alpha
__device__ float g_awep [4 * BB * ENC];   // alpha@x partials (K split 4)
__device__ float g_iw   [BB * ENC];
__device__ float g_inpp [2 * BB * ND];    // iw@W1 partials (K split 2)

// ---------------- packed f32x2 helpers ----------------
__device__ __forceinline__ ull pk2(float lo, float hi) {
    ull r; asm("mov.b64 %0, {%1, %2};" : "=l"(r) : "f"(lo), "f"(hi)); return r;
}
__device__ __forceinline__ void ffma2(ull& d, ull a, ull b) {
    asm("fma.rn.f32x2 %0, %1, %2, %0;" : "+l"(d) : "l"(a), "l"(b));
}
union F2U { ull u; float2 f; };

// ---------------- 64x128 GEMM tile, packed FMA2 ----------------
// Computes partial C[bm:bm+64, bn:bn+128] = sum_{k0..k0+KC} A[m,k]*B[k,n]
// 256 threads: tx=tid&31 (4 cols each), ty=tid>>5 (8 rows each, as 4 row-pairs)
template <int KC>
__device__ __forceinline__ void gemm_tile(const float* __restrict__ A, int lda,
                                          const float* __restrict__ B, int ldb,
                                          float* __restrict__ C, int ldc,
                                          int bm, int bn, int k0) {
    __shared__ __align__(16) float As[16][66];   // [k][row], padded: stride 66 (8B-aligned pairs, conflict-free)
    __shared__ __align__(16) float Bs[16][128];  // [k][col]
    const int tid = threadIdx.x;
    const int tx = tid & 31, ty = tid >> 5;

    ull acc[4][4];
    #pragma unroll
    for (int i = 0; i < 4; i++)
        #pragma unroll
        for (int j = 0; j < 4; j++) acc[i][j] = 0ull;

    for (int kb = 0; kb < KC; kb += 16) {
        // A tile 64x16 -> transposed store As[k][row]
        #pragma unroll
        for (int i = 0; i < 4; i++) {
            int idx = tid + i * 256;
            int r = idx >> 4, c = idx & 15;
            As[c][r] = A[(size_t)(bm + r) * lda + k0 + kb + c];
        }
        // B tile 16x128
        #pragma unroll
        for (int i = 0; i < 8; i++) {
            int idx = tid + i * 256;
            int c = idx & 127, r = idx >> 7;
            Bs[r][c] = B[(size_t)(k0 + kb + r) * ldb + bn + c];
        }
        __syncthreads();
        #pragma unroll
        for (int kk = 0; kk < 16; kk++) {
            ull a0 = *(const ull*)&As[kk][ty * 8 + 0];
            ull a1 = *(const ull*)&As[kk][ty * 8 + 2];
            ull a2 = *(const ull*)&As[kk][ty * 8 + 4];
            ull a3 = *(const ull*)&As[kk][ty * 8 + 6];
            float4 bv = *(const float4*)&Bs[kk][tx * 4];
            ull b0 = pk2(bv.x, bv.x);
            ull b1 = pk2(bv.y, bv.y);
            ull b2 = pk2(bv.z, bv.z);
            ull b3 = pk2(bv.w, bv.w);
            ffma2(acc[0][0], a0, b0); ffma2(acc[0][1], a0, b1); ffma2(acc[0][2], a0, b2); ffma2(acc[0][3], a0, b3);
            ffma2(acc[1][0], a1, b0); ffma2(acc[1][1], a1, b1); ffma2(acc[1][2], a1, b2); ffma2(acc[1][3], a1, b3);
            ffma2(acc[2][0], a2, b0); ffma2(acc[2][1], a2, b1); ffma2(acc[2][2], a2, b2); ffma2(acc[2][3], a2, b3);
            ffma2(acc[3][0], a3, b0); ffma2(acc[3][1], a3, b1); ffma2(acc[3][2], a3, b2); ffma2(acc[3][3], a3, b3);
        }
        __syncthreads();
    }
    // epilogue: 8 vectorized row stores
    #pragma unroll
    for (int i = 0; i < 4; i++) {
        F2U u0, u1, u2, u3;
        u0.u = acc[i][0]; u1.u = acc[i][1]; u2.u = acc[i][2]; u3.u = acc[i][3];
        int r0 = bm + ty * 8 + 2 * i;
        float4 lo = make_float4(u0.f.x, u1.f.x, u2.f.x, u3.f.x);
        float4 hi = make_float4(u0.f.y, u1.f.y, u2.f.y, u3.f.y);
        *(float4*)&C[(size_t)r0 * ldc + bn + tx * 4] = lo;
        *(float4*)&C[(size_t)(r0 + 1) * ldc + bn + tx * 4] = hi;
    }
}

// ---------------- P1: fused att1 + att2 + st partials (448 CTAs) ----------
__global__ void p1_kernel(const float* __restrict__ x, const float* __restrict__ state,
                          const float* __restrict__ We, const float* __restrict__ Wd,
                          const float* __restrict__ W2) {
    int id = blockIdx.x;
    if (id < 64) {                                   // att1: x@We, K=512 split 2
        int m = id & 7, r = id >> 3, n = r & 3, ks = r >> 2;
        gemm_tile<256>(x, ENC, We, ATT, g_att1p + (size_t)ks * BB * ATT, ATT,
                       m * 64, n * 128, ks * 256);
    } else if (id < 192) {                           // att2: state@Wd, K=1024 split 4
        int t = id - 64;
        int m = t & 7, r = t >> 3, n = r & 3, ks = r >> 2;
        gemm_tile<256>(state, ND, Wd, ATT, g_att2p + (size_t)ks * BB * ATT, ATT,
                       m * 64, n * 128, ks * 256);
    } else {                                         // st: state@W2, K=1024 split 4
        int t = id - 192;
        int m = t & 7, r = t >> 3, n = r & 7, ks = r >> 3;
        gemm_tile<256>(state, ND, W2, ND, g_stp + (size_t)ks * BB * ND, ND,
                       m * 64, n * 128, ks * 256);
    }
}

// ---------------- combine att1/att2 (+biases) ----------------
__global__ void combineA_kernel(const float* __restrict__ be, const float* __restrict__ bd) {
    int g = blockIdx.x * blockDim.x + threadIdx.x;   // float4 index
    const int Q = BB * ATT / 4;                      // 65536
    if (g < Q) {
        const float4* p0 = (const float4*)g_att1p;
        const float4* p1 = p0 + Q;
        float4 b = ((const float4*)be)[g & (ATT / 4 - 1)];
        float4 a = p0[g], c = p1[g];
        ((float4*)g_att1)[g] = make_float4(a.x + c.x + b.x, a.y + c.y + b.y,
                                           a.z + c.z + b.z, a.w + c.w + b.w);
    } else {
        g -= Q;
        const float4* p = (const float4*)g_att2p;
        float4 a0 = p[g], a1 = p[g + Q], a2 = p[g + 2 * Q], a3 = p[g + 3 * Q];
        float4 b = ((const float4*)bd)[g & (ATT / 4 - 1)];
        ((float4*)g_att2)[g] = make_float4(a0.x + a1.x + a2.x + a3.x + b.x,
                                           a0.y + a1.y + a2.y + a3.y + b.y,
                                           a0.z + a1.z + a2.z + a3.z + b.z,
                                           a0.w + a1.w + a2.w + a3.w + b.w);
    }
}

// ---------------- attention core: channel-split x4 (256 CTAs) ------------
// attp[z][q,k] = sum_{c in chunk z} relu(att1[k,c]+att2[q,c]) * Wf[c]
__global__ void attcore_kernel(const float* __restrict__ Wf) {
    __shared__ float Aq[64][16];
    __shared__ float Akt[16][65];
    __shared__ float ws[16];
    const int tx = threadIdx.x, ty = threadIdx.y;
    const int tid = ty * 16 + tx;
    const int bq = blockIdx.y * 64, bk = blockIdx.x * 64;
    const int z = blockIdx.z;

    float acc[4][4] = {};

    for (int c0 = z * 128; c0 < z * 128 + 128; c0 += 16) {
        #pragma unroll
        for (int i = 0; i < 4; i++) {
            int idx = tid + i * 256;
            int r = idx >> 4, c = idx & 15;
            Aq[r][c] = g_att2[(size_t)(bq + r) * ATT + c0 + c];
            Akt[c][r] = g_att1[(size_t)(bk + r) * ATT + c0 + c];
        }
        if (tid < 16) ws[tid] = Wf[c0 + tid];
        __syncthreads();
        #pragma unroll
        for (int cc = 0; cc < 16; cc++) {
            float wv = ws[cc];
            float aq0 = Aq[ty * 4 + 0][cc];
            float aq1 = Aq[ty * 4 + 1][cc];
            float aq2 = Aq[ty * 4 + 2][cc];
            float aq3 = Aq[ty * 4 + 3][cc];
            float ak0 = Akt[cc][tx * 4 + 0];
            float ak1 = Akt[cc][tx * 4 + 1];
            float ak2 = Akt[cc][tx * 4 + 2];
            float ak3 = Akt[cc][tx * 4 + 3];
            acc[0][0] += fmaxf(aq0 + ak0, 0.f) * wv; acc[0][1] += fmaxf(aq0 + ak1, 0.f) * wv;
            acc[0][2] += fmaxf(aq0 + ak2, 0.f) * wv; acc[0][3] += fmaxf(aq0 + ak3, 0.f) * wv;
            acc[1][0] += fmaxf(aq1 + ak0, 0.f) * wv; acc[1][1] += fmaxf(aq1 + ak1, 0.f) * wv;
            acc[1][2] += fmaxf(aq1 + ak2, 0.f) * wv; acc[1][3] += fmaxf(aq1 + ak3, 0.f) * wv;
            acc[2][0] += fmaxf(aq2 + ak0, 0.f) * wv; acc[2][1] += fmaxf(aq2 + ak1, 0.f) * wv;
            acc[2][2] += fmaxf(aq2 + ak2, 0.f) * wv; acc[2][3] += fmaxf(aq2 + ak3, 0.f) * wv;
            acc[3][0] += fmaxf(aq3 + ak0, 0.f) * wv; acc[3][1] += fmaxf(aq3 + ak1, 0.f) * wv;
            acc[3][2] += fmaxf(aq3 + ak2, 0.f) * wv; acc[3][3] += fmaxf(aq3 + ak3, 0.f) * wv;
        }
        __syncthreads();
    }
    float* out = g_attp + (size_t)z * BB * BB;
    #pragma unroll
    for (int i = 0; i < 4; i++)
        #pragma unroll
        for (int j = 0; j < 4; j++)
            out[(size_t)(bq + ty * 4 + i) * BB + bk + tx * 4 + j] = acc[i][j];
}

// ---------------- softmax (sums 4 channel partials, writes alpha) --------
__global__ void softmax_kernel() {
    const int row = blockIdx.x;
    const int t = threadIdx.x;   // 128 threads
    __shared__ float red[4];
    const size_t ro = (size_t)row * BB;
    const size_t Q = (size_t)BB * BB;
    float v[4];
    float m = -1e30f;
    #pragma unroll
    for (int i = 0; i < 4; i++) {
        size_t idx = ro + t + i * 128;
        v[i] = g_attp[idx] + g_attp[idx + Q] + g_attp[idx + 2 * Q] + g_attp[idx + 3 * Q];
        m = fmaxf(m, v[i]);
    }
    #pragma unroll
    for (int o = 16; o; o >>= 1) m = fmaxf(m, __shfl_xor_sync(~0u, m, o));
    if ((t & 31) == 0) red[t >> 5] = m;
    __syncthreads();
    m = fmaxf(fmaxf(red[0], red[1]), fmaxf(red[2], red[3]));
    float s = 0.f;
    #pragma unroll
    for (int i = 0; i < 4; i++) { v[i] = __expf(v[i] - m); s += v[i]; }
    #pragma unroll
    for (int o = 16; o; o >>= 1) s += __shfl_xor_sync(~0u, s, o);
    __syncthreads();
    if ((t & 31) == 0) red[t >> 5] = s;
    __syncthreads();
    s = red[0] + red[1] + red[2] + red[3];
    float inv = 1.0f / s;
    #pragma unroll
    for (int i = 0; i < 4; i++)
        g_att[ro + t + i * 128] = v[i] * inv;
}

// ---------------- P4: awe partials = alpha @ x (128 CTAs, K split 4) -----
__global__ void p4_kernel(const float* __restrict__ x) {
    int id = blockIdx.x;
    int m = id & 7, r = id >> 3, n = r & 3, ks = r >> 2;
    gemm_tile<128>(g_att, BB, x, ENC, g_awep + (size_t)ks * BB * ENC, ENC,
                   m * 64, n * 128, ks * 128);
}

// ---------------- combine iw = (sum awep) * x ----------------
__global__ void combine_iw_kernel(const float* __restrict__ x) {
    int g = blockIdx.x * blockDim.x + threadIdx.x;   // float4 index, 65536 total
    const int Q = BB * ENC / 4;
    const float4* p = (const float4*)g_awep;
    float4 a0 = p[g], a1 = p[g + Q], a2 = p[g + 2 * Q], a3 = p[g + 3 * Q];
    float4 xv = ((const float4*)x)[g];
    ((float4*)g_iw)[g] = make_float4((a0.x + a1.x + a2.x + a3.x) * xv.x,
                                     (a0.y + a1.y + a2.y + a3.y) * xv.y,
                                     (a0.z + a1.z + a2.z + a3.z) * xv.z,
                                     (a0.w + a1.w + a2.w + a3.w) * xv.w);
}

// ---------------- P5: inp partials = iw @ W1 (128 CTAs, K split 2) -------
__global__ void p5_kernel(const float* __restrict__ W1) {
    int id = blockIdx.x;
    int m = id & 7, r = id >> 3, n = r & 7, ks = r >> 3;
    gemm_tile<256>(g_iw, ENC, W1, ND, g_inpp + (size_t)ks * BB * ND, ND,
                   m * 64, n * 128, ks * 256);
}

// ---------------- combine new_state = relu(st + inp + b1 + b2) -----------
__global__ void combine_ns_kernel(const float* __restrict__ b1, const float* __restrict__ b2,
                                  float* __restrict__ new_state) {
    int g = blockIdx.x * blockDim.x + threadIdx.x;   // float4 index, 131072 total
    const int Q = BB * ND / 4;
    const float4* ip = (const float4*)g_inpp;
    const float4* sp = (const float4*)g_stp;
    float4 i0 = ip[g], i1 = ip[g + Q];
    float4 s0 = sp[g], s1 = sp[g + Q], s2 = sp[g + 2 * Q], s3 = sp[g + 3 * Q];
    int c4 = g & (ND / 4 - 1);
    float4 bb1 = ((const float4*)b1)[c4];
    float4 bb2 = ((const float4*)b2)[c4];
    float4 o;
    o.x = fmaxf(i0.x + i1.x + s0.x + s1.x + s2.x + s3.x + bb1.x + bb2.x, 0.f);
    o.y = fmaxf(i0.y + i1.y + s0.y + s1.y + s2.y + s3.y + bb1.y + bb2.y, 0.f);
    o.z = fmaxf(i0.z + i1.z + s0.z + s1.z + s2.z + s3.z + bb1.z + bb2.z, 0.f);
    o.w = fmaxf(i0.w + i1.w + s0.w + s1.w + s2.w + s3.w + bb1.w + bb2.w, 0.f);
    ((float4*)new_state)[g] = o;
}

// ---------------- thin output GEMM ----------------
__global__ void out_kernel(const float* __restrict__ ns, const float* __restrict__ W3,
                           const float* __restrict__ b3, float* __restrict__ out) {
    int gtid = blockIdx.x * blockDim.x + threadIdx.x;
    int row = gtid >> 5;
    int lane = gtid & 31;
    if (row >= BB) return;
    float s0 = 0.f, s1 = 0.f;
    for (int k = lane; k < ND; k += 32) {
        float v = ns[(size_t)row * ND + k];
        s0 += v * W3[k * 2 + 0];
        s1 += v * W3[k * 2 + 1];
    }
    #pragma unroll
    for (int o = 16; o; o >>= 1) {
        s0 += __shfl_down_sync(~0u, s0, o);
        s1 += __shfl_down_sync(~0u, s1, o);
    }
    if (lane == 0) {
        out[row * 2 + 0] = s0 + b3[0];
        out[row * 2 + 1] = s1 + b3[1];
    }
}

extern "C" void kernel_launch(void* const* d_in, const int* in_sizes, int n_in,
                              void* d_out, int out_size) {
    const float* x     = (const float*)d_in[0];
    const float* state = (const float*)d_in[1];
    const float* We    = (const float*)d_in[2];
    const float* be    = (const float*)d_in[3];
    const float* Wd    = (const float*)d_in[4];
    const float* bd    = (const float*)d_in[5];
    const float* Wf    = (const float*)d_in[6];
    // d_in[7] = bf : constant shift of all softmax logits -> mathematically irrelevant
    const float* W1    = (const float*)d_in[8];
    const float* b1    = (const float*)d_in[9];
    const float* W2    = (const float*)d_in[10];
    const float* b2    = (const float*)d_in[11];
    const float* W3    = (const float*)d_in[12];
    const float* b3    = (const float*)d_in[13];

    float* out = (float*)d_out;            // [0,1024): output ; then new_state (512x1024)
    float* new_state = out + BB * 2;

    p1_kernel<<<448, 256>>>(x, state, We, Wd, W2);
    combineA_kernel<<<512, 256>>>(be, bd);
    attcore_kernel<<<dim3(8, 8, 4), dim3(16, 16)>>>(Wf);
    softmax_kernel<<<BB, 128>>>();
    p4_kernel<<<128, 256>>>(x);
    combine_iw_kernel<<<256, 256>>>(x);
    p5_kernel<<<128, 256>>>(W1);
    combine_ns_kernel<<<512, 256>>>(b1, b2, new_state);
    out_kernel<<<(BB * 32 + 255) / 256, 256>>>(new_state, W3, b3, out);
}

// round 3
// speedup vs baseline: 2.2212x; 1.0185x over previous
#include <cuda_runtime.h>
#include <cuda_bf16.h>

#define BB   512
#define ENC  512
#define ATT  512
#define ND   1024

typedef unsigned long long ull;

// ---------------- scratch ----------------
__device__ float g_att1p[2 * BB * ATT];   // x@We partials (K split 2)
__device__ float g_att2p[4 * BB * ATT];   // state@Wd partials (K split 4)
__device__ float g_stp  [4 * BB * ND];    // state@W2 partials (K split 4)
__device__ float g_att1 [BB * ATT];       // (att1 + be) * Wf   (prescaled)
__device__ float g_att2 [BB * ATT];       // (att2 + bd) * Wf   (prescaled)
__device__ float g_attp [8 * BB * BB];    // logit partials (channel split 8)
__device__ float g_att  [BB * BB];        // alpha
__device__ float g_awep [4 * BB * ENC];   // alpha@x partials (K split 4)
__device__ float g_iw   [BB * ENC];
__device__ float g_inpp [2 * BB * ND];    // iw@W1 partials (K split 2)

// ---------------- packed f32x2 helpers ----------------
__device__ __forceinline__ ull pk2(float lo, float hi) {
    ull r; asm("mov.b64 %0, {%1, %2};" : "=l"(r) : "f"(lo), "f"(hi)); return r;
}
__device__ __forceinline__ void ffma2(ull& d, ull a, ull b) {
    asm("fma.rn.f32x2 %0, %1, %2, %0;" : "+l"(d) : "l"(a), "l"(b));
}
__device__ __forceinline__ ull add2(ull a, ull b) {
    ull r; asm("add.rn.f32x2 %0, %1, %2;" : "=l"(r) : "l"(a), "l"(b)); return r;
}
union F2U { ull u; float2 f; };
union U4  { float4 f; ull u[2]; };

// ---------------- 64x128 GEMM tile, packed FMA2 ----------------
// partial C[bm:bm+64, bn:bn+128] = sum_{k0..k0+KC} A[m,k]*B[k,n]
// 256 threads: tx=tid&31 (4 cols), ty=tid>>5 (8 rows = 4 row-pairs, warp-uniform)
template <int KC>
__device__ __forceinline__ void gemm_tile(const float* __restrict__ A, int lda,
                                          const float* __restrict__ B, int ldb,
                                          float* __restrict__ C, int ldc,
                                          int bm, int bn, int k0) {
    __shared__ __align__(16) float As[16][68];   // [k][row]; 68*4=272B rows, 16B-aligned
    __shared__ __align__(16) float Bs[16][128];  // [k][col]
    const int tid = threadIdx.x;
    const int tx = tid & 31, ty = tid >> 5;

    ull acc[4][4];
    #pragma unroll
    for (int i = 0; i < 4; i++)
        #pragma unroll
        for (int j = 0; j < 4; j++) acc[i][j] = 0ull;

    for (int kb = 0; kb < KC; kb += 16) {
        #pragma unroll
        for (int i = 0; i < 4; i++) {
            int idx = tid + i * 256;
            int r = idx >> 4, c = idx & 15;
            As[c][r] = A[(size_t)(bm + r) * lda + k0 + kb + c];
        }
        #pragma unroll
        for (int i = 0; i < 8; i++) {
            int idx = tid + i * 256;
            int c = idx & 127, r = idx >> 7;
            Bs[r][c] = B[(size_t)(k0 + kb + r) * ldb + bn + c];
        }
        __syncthreads();
        #pragma unroll
        for (int kk = 0; kk < 16; kk++) {
            U4 alo, ahi;                                     // 2x LDS.128 broadcast
            alo.f = *(const float4*)&As[kk][ty * 8 + 0];
            ahi.f = *(const float4*)&As[kk][ty * 8 + 4];
            ull a0 = alo.u[0], a1 = alo.u[1], a2 = ahi.u[0], a3 = ahi.u[1];
            float4 bv = *(const float4*)&Bs[kk][tx * 4];
            ull b0 = pk2(bv.x, bv.x);
            ull b1 = pk2(bv.y, bv.y);
            ull b2 = pk2(bv.z, bv.z);
            ull b3 = pk2(bv.w, bv.w);
            ffma2(acc[0][0], a0, b0); ffma2(acc[0][1], a0, b1); ffma2(acc[0][2], a0, b2); ffma2(acc[0][3], a0, b3);
            ffma2(acc[1][0], a1, b0); ffma2(acc[1][1], a1, b1); ffma2(acc[1][2], a1, b2); ffma2(acc[1][3], a1, b3);
            ffma2(acc[2][0], a2, b0); ffma2(acc[2][1], a2, b1); ffma2(acc[2][2], a2, b2); ffma2(acc[2][3], a2, b3);
            ffma2(acc[3][0], a3, b0); ffma2(acc[3][1], a3, b1); ffma2(acc[3][2], a3, b2); ffma2(acc[3][3], a3, b3);
        }
        __syncthreads();
    }
    #pragma unroll
    for (int i = 0; i < 4; i++) {
        F2U u0, u1, u2, u3;
        u0.u = acc[i][0]; u1.u = acc[i][1]; u2.u = acc[i][2]; u3.u = acc[i][3];
        int r0 = bm + ty * 8 + 2 * i;
        float4 lo = make_float4(u0.f.x, u1.f.x, u2.f.x, u3.f.x);
        float4 hi = make_float4(u0.f.y, u1.f.y, u2.f.y, u3.f.y);
        *(float4*)&C[(size_t)r0 * ldc + bn + tx * 4] = lo;
        *(float4*)&C[(size_t)(r0 + 1) * ldc + bn + tx * 4] = hi;
    }
}

// ---------------- P1: fused att1 + att2 + st partials (448 CTAs) ----------
__global__ __launch_bounds__(256) void p1_kernel(const float* __restrict__ x, const float* __restrict__ state,
                          const float* __restrict__ We, const float* __restrict__ Wd,
                          const float* __restrict__ W2) {
    int id = blockIdx.x;
    if (id < 64) {
        int m = id & 7, r = id >> 3, n = r & 3, ks = r >> 2;
        gemm_tile<256>(x, ENC, We, ATT, g_att1p + (size_t)ks * BB * ATT, ATT,
                       m * 64, n * 128, ks * 256);
    } else if (id < 192) {
        int t = id - 64;
        int m = t & 7, r = t >> 3, n = r & 3, ks = r >> 2;
        gemm_tile<256>(state, ND, Wd, ATT, g_att2p + (size_t)ks * BB * ATT, ATT,
                       m * 64, n * 128, ks * 256);
    } else {
        int t = id - 192;
        int m = t & 7, r = t >> 3, n = r & 7, ks = r >> 3;
        gemm_tile<256>(state, ND, W2, ND, g_stp + (size_t)ks * BB * ND, ND,
                       m * 64, n * 128, ks * 256);
    }
}

// ---- combine att1/att2 (+biases), prescaled by Wf (exact refactor) ------
__global__ void combineA_kernel(const float* __restrict__ be, const float* __restrict__ bd,
                                const float* __restrict__ Wf) {
    int g = blockIdx.x * blockDim.x + threadIdx.x;   // float4 index
    const int Q = BB * ATT / 4;
    if (g < Q) {
        const float4* p0 = (const float4*)g_att1p;
        const float4* p1 = p0 + Q;
        int c4 = g & (ATT / 4 - 1);
        float4 b = ((const float4*)be)[c4];
        float4 w = ((const float4*)Wf)[c4];
        float4 a = p0[g], c = p1[g];
        ((float4*)g_att1)[g] = make_float4((a.x + c.x + b.x) * w.x, (a.y + c.y + b.y) * w.y,
                                           (a.z + c.z + b.z) * w.z, (a.w + c.w + b.w) * w.w);
    } else {
        g -= Q;
        const float4* p = (const float4*)g_att2p;
        float4 a0 = p[g], a1 = p[g + Q], a2 = p[g + 2 * Q], a3 = p[g + 3 * Q];
        int c4 = g & (ATT / 4 - 1);
        float4 b = ((const float4*)bd)[c4];
        float4 w = ((const float4*)Wf)[c4];
        ((float4*)g_att2)[g] = make_float4((a0.x + a1.x + a2.x + a3.x + b.x) * w.x,
                                           (a0.y + a1.y + a2.y + a3.y + b.y) * w.y,
                                           (a0.z + a1.z + a2.z + a3.z + b.z) * w.z,
                                           (a0.w + a1.w + a2.w + a3.w + b.w) * w.w);
    }
}

// ---------------- attention core, packed f32x2 (256 CTAs) ----------------
// attp[z][q,k] = sum_{c in chunk z} pm_c(a1'[k,c] + a2'[q,c], 0)
// pm_c = max if Wf[c]>0 else min.   Tile: 128k x 64q x 64c.
__global__ __launch_bounds__(256) void attcore_kernel(const float* __restrict__ Wf) {
    __shared__ __align__(16) float A1[16][132];   // [c][k], 132*4=528B rows (16B-aligned)
    __shared__ __align__(16) float A2[16][132];   // [c][2q] duplicated pairs
    __shared__ float wsg[16];
    const int tid = threadIdx.x;
    const int tx = tid & 31;          // k: 4 cols at tx*4
    const int ty = tid >> 5;          // q: 8 rows at ty*8 (warp-uniform)
    const int bk = blockIdx.x * 128, bq = blockIdx.y * 64;
    const int c0base = blockIdx.z * 64;

    ull acc[8][2];
    #pragma unroll
    for (int i = 0; i < 8; i++) { acc[i][0] = 0ull; acc[i][1] = 0ull; }

    for (int ct = 0; ct < 4; ct++) {
        const int cb = c0base + ct * 16;
        // a1 tile: 16c x 128k (c contiguous in gmem -> coalesced 64B)
        #pragma unroll
        for (int i = 0; i < 8; i++) {
            int idx = tid + i * 256;
            int c = idx & 15, k = idx >> 4;
            A1[c][k] = g_att1[(size_t)(bk + k) * ATT + cb + c];
        }
        // a2 tile duplicated: 16c x 64q
        #pragma unroll
        for (int i = 0; i < 4; i++) {
            int idx = tid + i * 256;
            int c = idx & 15, q = idx >> 4;
            float v = g_att2[(size_t)(bq + q) * ATT + cb + c];
            *(float2*)&A2[c][2 * q] = make_float2(v, v);
        }
        if (tid < 16) wsg[tid] = Wf[cb + tid];
        __syncthreads();

        #pragma unroll
        for (int cc = 0; cc < 16; cc++) {
            U4 a1v; a1v.f = *(const float4*)&A1[cc][tx * 4];           // 2 k-pairs
            U4 q01, q23, q45, q67;                                     // 8 dup q-pairs
            q01.f = *(const float4*)&A2[cc][16 * ty + 0];
            q23.f = *(const float4*)&A2[cc][16 * ty + 4];
            q45.f = *(const float4*)&A2[cc][16 * ty + 8];
            q67.f = *(const float4*)&A2[cc][16 * ty + 12];
            ull qd[8] = { q01.u[0], q01.u[1], q23.u[0], q23.u[1],
                          q45.u[0], q45.u[1], q67.u[0], q67.u[1] };
            if (wsg[cc] > 0.0f) {
                #pragma unroll
                for (int q = 0; q < 8; q++) {
                    #pragma unroll
                    for (int p = 0; p < 2; p++) {
                        F2U t; t.u = add2(a1v.u[p], qd[q]);
                        t.f.x = fmaxf(t.f.x, 0.0f);
                        t.f.y = fmaxf(t.f.y, 0.0f);
                        acc[q][p] = add2(acc[q][p], t.u);
                    }
                }
            } else {
                #pragma unroll
                for (int q = 0; q < 8; q++) {
                    #pragma unroll
                    for (int p = 0; p < 2; p++) {
                        F2U t; t.u = add2(a1v.u[p], qd[q]);
                        t.f.x = fminf(t.f.x, 0.0f);
                        t.f.y = fminf(t.f.y, 0.0f);
                        acc[q][p] = add2(acc[q][p], t.u);
                    }
                }
            }
        }
        __syncthreads();
    }
    float* out = g_attp + (size_t)blockIdx.z * BB * BB;
    #pragma unroll
    for (int q = 0; q < 8; q++) {
        F2U lo, hi; lo.u = acc[q][0]; hi.u = acc[q][1];
        float4 v = make_float4(lo.f.x, lo.f.y, hi.f.x, hi.f.y);
        *(float4*)&out[(size_t)(bq + ty * 8 + q) * BB + bk + tx * 4] = v;
    }
}

// ---------------- softmax (sums 8 channel partials, writes alpha) --------
__global__ void softmax_kernel() {
    const int row = blockIdx.x;
    const int t = threadIdx.x;   // 128 threads, float4 each
    __shared__ float red[4];
    const size_t Q = (size_t)BB * BB;
    const size_t base = (size_t)row * BB + t * 4;
    float4 s4 = make_float4(0.f, 0.f, 0.f, 0.f);
    #pragma unroll
    for (int z = 0; z < 8; z++) {
        float4 p = *(const float4*)&g_attp[base + z * Q];
        s4.x += p.x; s4.y += p.y; s4.z += p.z; s4.w += p.w;
    }
    float m = fmaxf(fmaxf(s4.x, s4.y), fmaxf(s4.z, s4.w));
    #pragma unroll
    for (int o = 16; o; o >>= 1) m = fmaxf(m, __shfl_xor_sync(~0u, m, o));
    if ((t & 31) == 0) red[t >> 5] = m;
    __syncthreads();
    m = fmaxf(fmaxf(red[0], red[1]), fmaxf(red[2], red[3]));
    s4.x = __expf(s4.x - m); s4.y = __expf(s4.y - m);
    s4.z = __expf(s4.z - m); s4.w = __expf(s4.w - m);
    float s = s4.x + s4.y + s4.z + s4.w;
    #pragma unroll
    for (int o = 16; o; o >>= 1) s += __shfl_xor_sync(~0u, s, o);
    __syncthreads();
    if ((t & 31) == 0) red[t >> 5] = s;
    __syncthreads();
    s = red[0] + red[1] + red[2] + red[3];
    float inv = 1.0f / s;
    *(float4*)&g_att[base] = make_float4(s4.x * inv, s4.y * inv, s4.z * inv, s4.w * inv);
}

// ---------------- P4: awe partials = alpha @ x (128 CTAs, K split 4) -----
__global__ __launch_bounds__(256) void p4_kernel(const float* __restrict__ x) {
    int id = blockIdx.x;
    int m = id & 7, r = id >> 3, n = r & 3, ks = r >> 2;
    gemm_tile<128>(g_att, BB, x, ENC, g_awep + (size_t)ks * BB * ENC, ENC,
                   m * 64, n * 128, ks * 128);
}

// ---------------- combine iw = (sum awep) * x ----------------
__global__ void combine_iw_kernel(const float* __restrict__ x) {
    int g = blockIdx.x * blockDim.x + threadIdx.x;
    const int Q = BB * ENC / 4;
    const float4* p = (const float4*)g_awep;
    float4 a0 = p[g], a1 = p[g + Q], a2 = p[g + 2 * Q], a3 = p[g + 3 * Q];
    float4 xv = ((const float4*)x)[g];
    ((float4*)g_iw)[g] = make_float4((a0.x + a1.x + a2.x + a3.x) * xv.x,
                                     (a0.y + a1.y + a2.y + a3.y) * xv.y,
                                     (a0.z + a1.z + a2.z + a3.z) * xv.z,
                                     (a0.w + a1.w + a2.w + a3.w) * xv.w);
}

// ---------------- P5: inp partials = iw @ W1 (128 CTAs, K split 2) -------
__global__ __launch_bounds__(256) void p5_kernel(const float* __restrict__ W1) {
    int id = blockIdx.x;
    int m = id & 7, r = id >> 3, n = r & 7, ks = r >> 3;
    gemm_tile<256>(g_iw, ENC, W1, ND, g_inpp + (size_t)ks * BB * ND, ND,
                   m * 64, n * 128, ks * 256);
}

// ---------------- combine new_state = relu(st + inp + b1 + b2) -----------
__global__ void combine_ns_kernel(const float* __restrict__ b1, const float* __restrict__ b2,
                                  float* __restrict__ new_state) {
    int g = blockIdx.x * blockDim.x + threadIdx.x;
    const int Q = BB * ND / 4;
    const float4* ip = (const float4*)g_inpp;
    const float4* sp = (const float4*)g_stp;
    float4 i0 = ip[g], i1 = ip[g + Q];
    float4 s0 = sp[g], s1 = sp[g + Q], s2 = sp[g + 2 * Q], s3 = sp[g + 3 * Q];
    int c4 = g & (ND / 4 - 1);
    float4 bb1 = ((const float4*)b1)[c4];
    float4 bb2 = ((const float4*)b2)[c4];
    float4 o;
    o.x = fmaxf(i0.x + i1.x + s0.x + s1.x + s2.x + s3.x + bb1.x + bb2.x, 0.f);
    o.y = fmaxf(i0.y + i1.y + s0.y + s1.y + s2.y + s3.y + bb1.y + bb2.y, 0.f);
    o.z = fmaxf(i0.z + i1.z + s0.z + s1.z + s2.z + s3.z + bb1.z + bb2.z, 0.f);
    o.w = fmaxf(i0.w + i1.w + s0.w + s1.w + s2.w + s3.w + bb1.w + bb2.w, 0.f);
    ((float4*)new_state)[g] = o;
}

// ---------------- thin output GEMM (vectorized) ----------------
__global__ void out_kernel(const float* __restrict__ ns, const float* __restrict__ W3,
                           const float* __restrict__ b3, float* __restrict__ out) {
    int gtid = blockIdx.x * blockDim.x + threadIdx.x;
    int row = gtid >> 5;
    int lane = gtid & 31;
    if (row >= BB) return;
    float s0 = 0.f, s1 = 0.f;
    #pragma unroll
    for (int i = 0; i < 8; i++) {
        int k = lane * 4 + i * 128;
        float4 v = *(const float4*)&ns[(size_t)row * ND + k];
        float4 w0 = *(const float4*)&W3[k * 2];
        float4 w1 = *(const float4*)&W3[k * 2 + 4];
        s0 += v.x * w0.x + v.y * w0.z + v.z * w1.x + v.w * w1.z;
        s1 += v.x * w0.y + v.y * w0.w + v.z * w1.y + v.w * w1.w;
    }
    #pragma unroll
    for (int o = 16; o; o >>= 1) {
        s0 += __shfl_down_sync(~0u, s0, o);
        s1 += __shfl_down_sync(~0u, s1, o);
    }
    if (lane == 0) {
        out[row * 2 + 0] = s0 + b3[0];
        out[row * 2 + 1] = s1 + b3[1];
    }
}

extern "C" void kernel_launch(void* const* d_in, const int* in_sizes, int n_in,
                              void* d_out, int out_size) {
    const float* x     = (const float*)d_in[0];
    const float* state = (const float*)d_in[1];
    const float* We    = (const float*)d_in[2];
    const float* be    = (const float*)d_in[3];
    const float* Wd    = (const float*)d_in[4];
    const float* bd    = (const float*)d_in[5];
    const float* Wf    = (const float*)d_in[6];
    // d_in[7] = bf : constant shift of all softmax logits -> mathematically irrelevant
    const float* W1    = (const float*)d_in[8];
    const float* b1    = (const float*)d_in[9];
    const float* W2    = (const float*)d_in[10];
    const float* b2    = (const float*)d_in[11];
    const float* W3    = (const float*)d_in[12];
    const float* b3    = (const float*)d_in[13];

    float* out = (float*)d_out;            // [0,1024): output ; then new_state (512x1024)
    float* new_state = out + BB * 2;

    p1_kernel<<<448, 256>>>(x, state, We, Wd, W2);
    combineA_kernel<<<512, 256>>>(be, bd, Wf);
    attcore_kernel<<<dim3(4, 8, 8), 256>>>(Wf);
    softmax_kernel<<<BB, 128>>>();
    p4_kernel<<<128, 256>>>(x);
    combine_iw_kernel<<<256, 256>>>(x);
    p5_kernel<<<128, 256>>>(W1);
    combine_ns_kernel<<<512, 256>>>(b1, b2, new_state);
    out_kernel<<<(BB * 32 + 255) / 256, 256>>>(new_state, W3, b3, out);
}